// round 2
// baseline (speedup 1.0000x reference)
#include <cuda_runtime.h>
#include <cuda_bf16.h>
#include <math.h>

// ---------------- problem constants ----------------
#define NN    8192
#define EE    262144
#define INC   64
#define OUTC  64
#define KK    3
#define GG    64
#define NC    10
#define DIN   192      // IN_C*K
#define DOUT  192      // OUT_C*K
#define D3    576      // DOUT*3
#define D2    384      // DOUT*2
#define BNEPS 1e-5f

// ---------------- device scratch (no allocation allowed) ----------------
__device__ int   g_flags[2];          // [0]=edge_index is int32?, [1]=batch is int32?
__device__ int   g_deg[NN];
__device__ float g_dinv[NN];
__device__ int   g_offs[NN + 1];
__device__ int   g_cnt[NN];
__device__ int   g_col[EE];
__device__ float g_Hcat[NN * DIN];    // [x | Lx | L^2 x]
__device__ float g_H[NN * DOUT];      // after masked linear (+b)
__device__ float g_Wm[DOUT * DIN];    // (W_orig/sigma) * mask
__device__ float g_invsigma;
__device__ float g_bnsum[DOUT];
__device__ float g_bnsq[DOUT];
__device__ float g_bna[DOUT];
__device__ float g_bnc[DOUT];
__device__ int   g_seg[GG + 1];
__device__ float g_Hg[GG * D3];
__device__ float g_Xg[GG * D3];
__device__ float g_F1[GG * D2];
__device__ float g_F2[GG * DOUT];

// ---------------- helpers ----------------
__device__ __forceinline__ int fetch_idx(const void* p, long long i, int is32) {
    if (is32) return ((const int*)p)[i];
    return (int)(((const long long*)p)[i]);
}

// ---------------- K0: init + robust dtype detection ----------------
// Detection: view the buffer as int64. If the true dtype is int64 (values small,
// non-negative), the high 32-bit word of every element is 0. If the true dtype
// is int32, the "high word" is really the NEXT int32 element, which is nonzero
// with overwhelming probability across spread probes (batch values near the end
// are ~G-1; edge indices are random in [0,N)). Probes are restricted to the
// first half of the int64-view so reads stay in-bounds for an int32-sized buffer.
__global__ void init_kernel(const void* ei, const void* batch) {
    int tid = blockIdx.x * blockDim.x + threadIdx.x;
    if (tid == 0) {
        const int* e32 = (const int*)ei;
        int is32_e = 0;
        for (int k = 0; k < 64; k++) {
            long long pe = (long long)k * (EE / 64);     // int64-element index < EE (first half of 2*EE)
            if (e32[2 * pe + 1] != 0) { is32_e = 1; break; }
        }
        g_flags[0] = is32_e;
        const int* b32p = (const int*)batch;
        int is32_b = 0;
        for (int k = 0; k < 64; k++) {
            long long pb = (long long)k * (NN / 128);    // int64-element index < NN/2
            if (b32p[2 * pb + 1] != 0) { is32_b = 1; break; }
        }
        g_flags[1] = is32_b;
    }
    for (int i = tid; i < NN; i += gridDim.x * blockDim.x) { g_deg[i] = 0; g_cnt[i] = 0; }
    for (int i = tid; i < DOUT; i += gridDim.x * blockDim.x) { g_bnsum[i] = 0.f; g_bnsq[i] = 0.f; }
}

// ---------------- K1: degree histogram ----------------
__global__ void degree_kernel(const void* ei) {
    int e = blockIdx.x * blockDim.x + threadIdx.x;
    if (e < EE) {
        int r = fetch_idx(ei, e, g_flags[0]);        // row = edge_index[0][e]
        atomicAdd(&g_deg[r], 1);
    }
}

// ---------------- K2: dinv ----------------
__global__ void dinv_kernel() {
    int i = blockIdx.x * blockDim.x + threadIdx.x;
    if (i < NN) {
        int d = g_deg[i];
        g_dinv[i] = (d > 0) ? rsqrtf((float)d) : 0.f;
    }
}

// ---------------- K3: exclusive scan of degrees (single block) ----------------
__global__ void scan_kernel() {
    __shared__ int s[1024];
    int t = threadIdx.x;
    int base = t * 8;
    int loc[8];
    int run = 0;
#pragma unroll
    for (int k = 0; k < 8; k++) { loc[k] = run; run += g_deg[base + k]; }
    s[t] = run;
    __syncthreads();
    for (int off = 1; off < 1024; off <<= 1) {
        int v = (t >= off) ? s[t - off] : 0;
        __syncthreads();
        if (t >= off) s[t] += v;
        __syncthreads();
    }
    int pre = (t > 0) ? s[t - 1] : 0;
#pragma unroll
    for (int k = 0; k < 8; k++) g_offs[base + k] = pre + loc[k];
    if (t == 1023) g_offs[NN] = s[1023];
}

// ---------------- K4: scatter edges into CSR ----------------
__global__ void scatter_kernel(const void* ei) {
    int e = blockIdx.x * blockDim.x + threadIdx.x;
    if (e < EE) {
        int is32 = g_flags[0];
        int r = fetch_idx(ei, e, is32);
        int c = fetch_idx(ei, (long long)EE + e, is32);
        int pos = g_offs[r] + atomicAdd(&g_cnt[r], 1);
        g_col[pos] = c;
    }
}

// ---------------- K5: copy x into Hcat[:, 0:64] ----------------
__global__ void copyx_kernel(const float* __restrict__ x) {
    int i = blockIdx.x * blockDim.x + threadIdx.x;
    if (i < NN * INC) {
        int r = i >> 6, c = i & 63;
        g_Hcat[r * DIN + c] = x[i];
    }
}

// ---------------- K6/K7: SpMM  out = (I - D^-1/2 A D^-1/2) @ in  (warp per node) ----------------
__global__ void spmm_kernel(const float* __restrict__ in, int ldin,
                            float* __restrict__ out, int ldout) {
    int gtid = blockIdx.x * blockDim.x + threadIdx.x;
    int node = gtid >> 5;
    int lane = gtid & 31;
    if (node >= NN) return;
    float di = g_dinv[node];
    int p = g_offs[node];
    int pe = g_offs[node + 1];
    float acc0 = 0.f, acc1 = 0.f;
    for (; p + 1 < pe; p += 2) {
        int c0 = g_col[p], c1 = g_col[p + 1];
        float w0 = g_dinv[c0], w1 = g_dinv[c1];
        const float* r0 = in + (long)c0 * ldin;
        const float* r1 = in + (long)c1 * ldin;
        acc0 += w0 * r0[lane] + w1 * r1[lane];
        acc1 += w0 * r0[lane + 32] + w1 * r1[lane + 32];
    }
    if (p < pe) {
        int c0 = g_col[p];
        float w0 = g_dinv[c0];
        const float* r0 = in + (long)c0 * ldin;
        acc0 += w0 * r0[lane];
        acc1 += w0 * r0[lane + 32];
    }
    const float* ri = in + (long)node * ldin;
    out[(long)node * ldout + lane]      = ri[lane]      - di * acc0;
    out[(long)node * ldout + lane + 32] = ri[lane + 32] - di * acc1;
}

// ---------------- K8: spectral sigma (one power-iter step), 1 block x 192 ----------------
__global__ void sigma_kernel(const float* __restrict__ W, const float* __restrict__ u) {
    __shared__ float v[DOUT];
    __shared__ float wsum[6];
    __shared__ float scal;
    int t = threadIdx.x;
    int lane = t & 31, wid = t >> 5;
    // v = W^T u
    float vt = 0.f;
    for (int i = 0; i < DOUT; i++) vt += W[i * DIN + t] * u[i];
    // ||v||
    float w = vt * vt;
#pragma unroll
    for (int o = 16; o > 0; o >>= 1) w += __shfl_xor_sync(0xffffffffu, w, o);
    if (lane == 0) wsum[wid] = w;
    __syncthreads();
    if (t == 0) {
        float s2 = 0.f;
        for (int k = 0; k < 6; k++) s2 += wsum[k];
        scal = sqrtf(s2) + 1e-12f;
    }
    __syncthreads();
    v[t] = vt / scal;
    __syncthreads();
    // sigma = u . (W v)
    float wv = 0.f;
    for (int j = 0; j < DIN; j++) wv += W[t * DIN + j] * v[j];
    float p = u[t] * wv;
#pragma unroll
    for (int o = 16; o > 0; o >>= 1) p += __shfl_xor_sync(0xffffffffu, p, o);
    if (lane == 0) wsum[wid] = p;
    __syncthreads();
    if (t == 0) {
        float sg = 0.f;
        for (int k = 0; k < 6; k++) sg += wsum[k];
        g_invsigma = 1.0f / sg;
    }
}

// ---------------- K9: masked scaled weight ----------------
__global__ void wm_kernel(const float* __restrict__ W) {
    int i = blockIdx.x * blockDim.x + threadIdx.x;
    if (i < DOUT * DIN) {
        int r = i / DIN, c = i % DIN;
        int blk = r / OUTC;                       // row block
        float m = (c < INC * (blk + 1)) ? 1.f : 0.f;
        g_Wm[i] = W[i] * g_invsigma * m;
    }
}

// ---------------- K10: tiled GEMM  H = Hcat @ Wm^T + b   [8192x192]x[192x192] ----------------
__global__ void gemm_kernel(const float* __restrict__ bias) {
    __shared__ float As[16][65];
    __shared__ float Bs[16][65];
    int t  = threadIdx.x;                 // 256
    int tx = t & 15, ty = t >> 4;
    int m0 = blockIdx.x * 64;
    int n0 = blockIdx.y * 64;
    int lm = t >> 2;                      // 0..63
    int lk = (t & 3) * 4;                 // 0,4,8,12
    float cr[4][4];
#pragma unroll
    for (int i = 0; i < 4; i++)
#pragma unroll
        for (int j = 0; j < 4; j++) cr[i][j] = 0.f;

    for (int k0 = 0; k0 < DIN; k0 += 16) {
        float4 av = *(const float4*)(g_Hcat + (long)(m0 + lm) * DIN + k0 + lk);
        As[lk + 0][lm] = av.x; As[lk + 1][lm] = av.y; As[lk + 2][lm] = av.z; As[lk + 3][lm] = av.w;
        float4 bv = *(const float4*)(g_Wm + (long)(n0 + lm) * DIN + k0 + lk);
        Bs[lk + 0][lm] = bv.x; Bs[lk + 1][lm] = bv.y; Bs[lk + 2][lm] = bv.z; Bs[lk + 3][lm] = bv.w;
        __syncthreads();
#pragma unroll
        for (int kk = 0; kk < 16; kk++) {
            float a0 = As[kk][ty * 4 + 0], a1 = As[kk][ty * 4 + 1];
            float a2 = As[kk][ty * 4 + 2], a3 = As[kk][ty * 4 + 3];
            float b0 = Bs[kk][tx * 4 + 0], b1 = Bs[kk][tx * 4 + 1];
            float b2 = Bs[kk][tx * 4 + 2], b3 = Bs[kk][tx * 4 + 3];
            cr[0][0] += a0 * b0; cr[0][1] += a0 * b1; cr[0][2] += a0 * b2; cr[0][3] += a0 * b3;
            cr[1][0] += a1 * b0; cr[1][1] += a1 * b1; cr[1][2] += a1 * b2; cr[1][3] += a1 * b3;
            cr[2][0] += a2 * b0; cr[2][1] += a2 * b1; cr[2][2] += a2 * b2; cr[2][3] += a2 * b3;
            cr[3][0] += a3 * b0; cr[3][1] += a3 * b1; cr[3][2] += a3 * b2; cr[3][3] += a3 * b3;
        }
        __syncthreads();
    }
#pragma unroll
    for (int i = 0; i < 4; i++) {
        int m = m0 + ty * 4 + i;
#pragma unroll
        for (int j = 0; j < 4; j++) {
            int n = n0 + tx * 4 + j;
            g_H[(long)m * DOUT + n] = cr[i][j] + bias[n];
        }
    }
}

// ---------------- K11: BN1 partial stats ----------------
__global__ void bnstats_kernel() {
    int j = threadIdx.x;                 // 192 channels
    int r0 = blockIdx.x * 64;
    float s = 0.f, q = 0.f;
    for (int r = 0; r < 64; r++) {
        float v = g_H[(long)(r0 + r) * DOUT + j];
        s += v; q += v * v;
    }
    atomicAdd(&g_bnsum[j], s);
    atomicAdd(&g_bnsq[j], q);
}

// ---------------- K12: BN1 scale/shift ----------------
__global__ void bnab_kernel(const float* __restrict__ gamma, const float* __restrict__ beta) {
    int j = threadIdx.x;
    float mu = g_bnsum[j] / (float)NN;
    float var = g_bnsq[j] / (float)NN - mu * mu;
    float a = gamma[j] * rsqrtf(var + BNEPS);
    g_bna[j] = a;
    g_bnc[j] = beta[j] - a * mu;
}

// ---------------- K13: segment boundaries (batch is sorted) ----------------
__global__ void seg_kernel(const void* batch) {
    int g = threadIdx.x;                 // 65 threads
    if (g > GG) return;
    if (g == GG) { g_seg[GG] = NN; return; }
    int is32 = g_flags[1];
    int lo = 0, hi = NN;
    while (lo < hi) {
        int mid = (lo + hi) >> 1;
        int v = fetch_idx(batch, mid, is32);
        if (v < g) lo = mid + 1; else hi = mid;
    }
    g_seg[g] = lo;
}

// ---------------- K14: apply BN1 + triple pooling (avg|sum|max) ----------------
__global__ void pool_kernel() {
    int g = blockIdx.x;                  // 64 graphs
    int j = threadIdx.x;                 // 192 channels
    int s = g_seg[g], e = g_seg[g + 1];
    float a = g_bna[j], c = g_bnc[j];
    float sum = 0.f, mx = -INFINITY;
    for (int r = s; r < e; r++) {
        float v = a * g_H[(long)r * DOUT + j] + c;
        sum += v;
        mx = fmaxf(mx, v);
    }
    float cnt = fmaxf((float)(e - s), 1.f);
    g_Hg[g * D3 + j]            = sum / cnt;   // avg
    g_Hg[g * D3 + DOUT + j]     = sum;         // sum
    g_Hg[g * D3 + 2 * DOUT + j] = mx;          // max
}

// ---------------- K15: BN2 over G ----------------
__global__ void bn2_kernel(const float* __restrict__ gamma, const float* __restrict__ beta) {
    int j = threadIdx.x;                 // 576
    float s = 0.f, q = 0.f;
    for (int r = 0; r < GG; r++) {
        float v = g_Hg[r * D3 + j];
        s += v; q += v * v;
    }
    float mu = s / (float)GG;
    float var = q / (float)GG - mu * mu;
    float a = gamma[j] * rsqrtf(var + BNEPS);
    float c = beta[j] - a * mu;
    for (int r = 0; r < GG; r++)
        g_Xg[r * D3 + j] = a * g_Hg[r * D3 + j] + c;
}

// ---------------- K16: FC1 relu ----------------
__global__ void fc1_kernel(const float* __restrict__ w1, const float* __restrict__ b1) {
    __shared__ float xr[D3];
    int g = blockIdx.x, j = threadIdx.x; // 384 threads
    for (int k = j; k < D3; k += D2) xr[k] = g_Xg[g * D3 + k];
    __syncthreads();
    float acc = b1[j];
    const float* wr = w1 + (long)j * D3;
#pragma unroll 4
    for (int k = 0; k < D3; k++) acc += xr[k] * wr[k];
    g_F1[g * D2 + j] = fmaxf(acc, 0.f);
}

// ---------------- K17: FC2 relu ----------------
__global__ void fc2_kernel(const float* __restrict__ w2, const float* __restrict__ b2) {
    __shared__ float xr[D2];
    int g = blockIdx.x, j = threadIdx.x; // 192 threads
    for (int k = j; k < D2; k += DOUT) xr[k] = g_F1[g * D2 + k];
    __syncthreads();
    float acc = b2[j];
    const float* wr = w2 + (long)j * D2;
#pragma unroll 4
    for (int k = 0; k < D2; k++) acc += xr[k] * wr[k];
    g_F2[g * DOUT + j] = fmaxf(acc, 0.f);
}

// ---------------- K18: FC3 + log_softmax ----------------
__global__ void fc3_kernel(const float* __restrict__ w3, const float* __restrict__ b3,
                           float* __restrict__ out) {
    int g = blockIdx.x, t = threadIdx.x; // 32 threads
    float logit = -INFINITY;
    if (t < NC) {
        float acc = b3[t];
        const float* xr = g_F2 + g * DOUT;
        const float* wr = w3 + t * DOUT;
        for (int k = 0; k < DOUT; k++) acc += xr[k] * wr[k];
        logit = acc;
    }
    float mx = logit;
#pragma unroll
    for (int o = 16; o > 0; o >>= 1) mx = fmaxf(mx, __shfl_xor_sync(0xffffffffu, mx, o));
    float ex = (t < NC) ? expf(logit - mx) : 0.f;
    float se = ex;
#pragma unroll
    for (int o = 16; o > 0; o >>= 1) se += __shfl_xor_sync(0xffffffffu, se, o);
    if (t < NC) out[g * NC + t] = logit - mx - logf(se);
}

// ---------------- launch ----------------
extern "C" void kernel_launch(void* const* d_in, const int* in_sizes, int n_in,
                              void* d_out, int out_size) {
    const float* x      = (const float*)d_in[0];
    const void*  ei     = d_in[1];
    const void*  batch  = d_in[2];
    const float* W_orig = (const float*)d_in[3];
    const float* b      = (const float*)d_in[4];
    const float* u      = (const float*)d_in[5];
    const float* bn1g   = (const float*)d_in[6];
    const float* bn1b   = (const float*)d_in[7];
    const float* bn2g   = (const float*)d_in[8];
    const float* bn2b   = (const float*)d_in[9];
    const float* w1     = (const float*)d_in[10];
    const float* b1     = (const float*)d_in[11];
    const float* w2     = (const float*)d_in[12];
    const float* b2     = (const float*)d_in[13];
    const float* w3     = (const float*)d_in[14];
    const float* b3     = (const float*)d_in[15];
    float* out = (float*)d_out;

    init_kernel<<<64, 256>>>(ei, batch);
    degree_kernel<<<EE / 256, 256>>>(ei);
    dinv_kernel<<<NN / 256, 256>>>();
    scan_kernel<<<1, 1024>>>();
    scatter_kernel<<<EE / 256, 256>>>(ei);
    copyx_kernel<<<(NN * INC) / 256, 256>>>(x);

    // SpMM 1: Hcat[:,64:128] = L @ x     (x has ld=64)
    {
        float* hcat_dev = nullptr;
        cudaGetSymbolAddress((void**)&hcat_dev, g_Hcat);
        spmm_kernel<<<NN * 32 / 256, 256>>>(x, INC, hcat_dev + INC, DIN);
        // SpMM 2: Hcat[:,128:192] = L @ Hcat[:,64:128]
        spmm_kernel<<<NN * 32 / 256, 256>>>(hcat_dev + INC, DIN, hcat_dev + 2 * INC, DIN);
    }

    sigma_kernel<<<1, DOUT>>>(W_orig, u);
    wm_kernel<<<(DOUT * DIN + 255) / 256, 256>>>(W_orig);

    dim3 ggrid(NN / 64, DOUT / 64);
    gemm_kernel<<<ggrid, 256>>>(b);

    bnstats_kernel<<<NN / 64, DOUT>>>();
    bnab_kernel<<<1, DOUT>>>(bn1g, bn1b);
    seg_kernel<<<1, GG + 1>>>(batch);
    pool_kernel<<<GG, DOUT>>>();
    bn2_kernel<<<1, D3>>>(bn2g, bn2b);
    fc1_kernel<<<GG, D2>>>(w1, b1);
    fc2_kernel<<<GG, DOUT>>>(w2, b2);
    fc3_kernel<<<GG, 32>>>(w3, b3, out);
}